// round 13
// baseline (speedup 1.0000x reference)
#include <cuda_runtime.h>
#include <cuda_bf16.h>
#include <math.h>
#include <stdint.h>

#define BB 4096
#define DD 256
#define TT 64

// ================= PTX helpers (baseline ISA only) =================
__device__ __forceinline__ uint32_t smem_u32(const void* p) {
    uint32_t a;
    asm("{ .reg .u64 t; cvta.to.shared.u64 t, %1; cvt.u32.u64 %0, t; }" : "=r"(a) : "l"(p));
    return a;
}
__device__ __forceinline__ void cp16(uint32_t saddr, const void* g) {
    asm volatile("cp.async.cg.shared.global [%0], [%1], 16;" :: "r"(saddr), "l"(g));
}
__device__ __forceinline__ void ldsm4(uint32_t* r, uint32_t addr) {
    asm volatile("ldmatrix.sync.aligned.m8n8.x4.shared.b16 {%0,%1,%2,%3}, [%4];"
        : "=r"(r[0]), "=r"(r[1]), "=r"(r[2]), "=r"(r[3]) : "r"(addr));
}
__device__ __forceinline__ void mma16816(float* c, const uint32_t* a, uint32_t b0, uint32_t b1) {
    asm volatile("mma.sync.aligned.m16n8k16.row.col.f32.bf16.bf16.f32 "
        "{%0,%1,%2,%3}, {%4,%5,%6,%7}, {%8,%9}, {%0,%1,%2,%3};"
        : "+f"(c[0]), "+f"(c[1]), "+f"(c[2]), "+f"(c[3])
        : "r"(a[0]), "r"(a[1]), "r"(a[2]), "r"(a[3]), "r"(b0), "r"(b1));
}

// ================= scratch pool =================
static constexpr size_t SZ_XG  = (size_t)BB * 768 * 2;
static constexpr size_t SZ_XS  = (size_t)BB * 512 * 2;
static constexpr size_t SZ_BD  = (size_t)BB * 256 * 2;
static constexpr size_t SZ_Q0  = (size_t)2 * BB * 256 * 2;
static constexpr size_t SZ_BDF = (size_t)BB * 256 * 4;

static constexpr size_t O_XG_H  = 0;
static constexpr size_t O_XG_L  = O_XG_H  + SZ_XG;
static constexpr size_t O_XE_H  = O_XG_L  + SZ_XG;
static constexpr size_t O_XE_L  = O_XE_H  + SZ_XG;
static constexpr size_t O_XQS_H = O_XE_L  + SZ_XG;
static constexpr size_t O_XQS_L = O_XQS_H + SZ_XS;
static constexpr size_t O_XRS_H = O_XQS_L + SZ_XS;
static constexpr size_t O_XRS_L = O_XRS_H + SZ_XS;
static constexpr size_t O_XPL_H = O_XRS_L + SZ_XS;
static constexpr size_t O_XPL_L = O_XPL_H + SZ_XS;
static constexpr size_t O_Q0_H  = O_XPL_L + SZ_XS;
static constexpr size_t O_Q0_L  = O_Q0_H  + SZ_Q0;
static constexpr size_t O_GH_H  = O_Q0_L  + SZ_Q0;
static constexpr size_t O_GH_L  = O_GH_H  + SZ_BD;
static constexpr size_t O_E0_H  = O_GH_L  + SZ_BD;
static constexpr size_t O_E0_L  = O_E0_H  + SZ_BD;
static constexpr size_t O_QS_H  = O_E0_L  + SZ_BD;
static constexpr size_t O_QS_L  = O_QS_H  + SZ_BD;
static constexpr size_t O_RS_H  = O_QS_L  + SZ_BD;
static constexpr size_t O_RS_L  = O_RS_H  + SZ_BD;
static constexpr size_t O_QSF   = O_RS_L  + SZ_BD;
static constexpr size_t O_RSF   = O_QSF   + SZ_BDF;
static constexpr size_t SZ_W768 = (size_t)768 * 768 * 2;
static constexpr size_t SZ_W512 = (size_t)768 * 512 * 2;
static constexpr size_t SZ_W256 = (size_t)768 * 256 * 2;
static constexpr size_t O_WGIH_H = O_RSF + SZ_BDF;
static constexpr size_t O_WGIH_L = O_WGIH_H + SZ_W768;
static constexpr size_t O_WGHH_H = O_WGIH_L + SZ_W768;
static constexpr size_t O_WGHH_L = O_WGHH_H + SZ_W256;
static constexpr size_t O_WPIH_H = O_WGHH_L + SZ_W256;
static constexpr size_t O_WPIH_L = O_WPIH_H + SZ_W512;
static constexpr size_t O_WPHH_H = O_WPIH_L + SZ_W512;
static constexpr size_t O_WPHH_L = O_WPHH_H + SZ_W256;
static constexpr size_t O_WLIH_H = O_WPHH_L + SZ_W256;
static constexpr size_t O_WLIH_L = O_WLIH_H + SZ_W512;
static constexpr size_t O_WLHH_H = O_WLIH_L + SZ_W512;
static constexpr size_t O_WLHH_L = O_WLHH_H + SZ_W256;
static constexpr size_t O_WRIH_H = O_WLHH_L + SZ_W256;
static constexpr size_t O_WRIH_L = O_WRIH_H + SZ_W512;
static constexpr size_t O_WRHH_H = O_WRIH_L + SZ_W512;
static constexpr size_t O_WRHH_L = O_WRHH_H + SZ_W256;
static constexpr size_t O_WEIH_H = O_WRHH_L + SZ_W256;
static constexpr size_t O_WEIH_L = O_WEIH_H + SZ_W768;
static constexpr size_t O_WEHH_H = O_WEIH_L + SZ_W768;
static constexpr size_t O_WEHH_L = O_WEHH_H + SZ_W256;
static constexpr size_t O_SELROW = O_WEHH_L + SZ_W256;
static constexpr size_t O_QMIDX  = O_SELROW + BB * 4;
static constexpr size_t POOL_SZ  = O_QMIDX + BB * 4;

__device__ __align__(1024) unsigned char g_pool[POOL_SZ];

// ================= helpers =================
__device__ __forceinline__ void bsplit(float x, __nv_bfloat16* hp, __nv_bfloat16* lp, size_t i) {
    __nv_bfloat16 h = __float2bfloat16(x);
    hp[i] = h;
    lp[i] = __float2bfloat16(x - __bfloat162float(h));
}

// ================= conv_all: vectorized x4 =================
struct ConvSeg { const float* src; __nv_bfloat16* hi; __nv_bfloat16* lo; int nblk; };
struct ConvTable { ConvSeg s[13]; };

__global__ void conv_all_kernel(ConvTable t) {
    int blk = blockIdx.x;
    #pragma unroll 1
    for (int i = 0; i < 13; i++) {
        int nb = t.s[i].nblk;
        if (blk < nb) {
            int idx = blk * 1024 + threadIdx.x * 4;
            float4 v = *(const float4*)(t.s[i].src + idx);
            __nv_bfloat16 h0 = __float2bfloat16(v.x);
            __nv_bfloat16 h1 = __float2bfloat16(v.y);
            __nv_bfloat16 h2 = __float2bfloat16(v.z);
            __nv_bfloat16 h3 = __float2bfloat16(v.w);
            __nv_bfloat16 l0 = __float2bfloat16(v.x - __bfloat162float(h0));
            __nv_bfloat16 l1 = __float2bfloat16(v.y - __bfloat162float(h1));
            __nv_bfloat16 l2 = __float2bfloat16(v.z - __bfloat162float(h2));
            __nv_bfloat16 l3 = __float2bfloat16(v.w - __bfloat162float(h3));
            __nv_bfloat162 hv0, hv1, lv0, lv1;
            hv0.x = h0; hv0.y = h1; hv1.x = h2; hv1.y = h3;
            lv0.x = l0; lv0.y = l1; lv1.x = l2; lv1.y = l3;
            *(__nv_bfloat162*)(t.s[i].hi + idx)     = hv0;
            *(__nv_bfloat162*)(t.s[i].hi + idx + 2) = hv1;
            *(__nv_bfloat162*)(t.s[i].lo + idx)     = lv0;
            *(__nv_bfloat162*)(t.s[i].lo + idx + 2) = lv1;
            return;
        }
        blk -= nb;
    }
}

// ================= prep =================
__global__ void prep_kernel(const float* __restrict__ U, const float* __restrict__ qmask,
                            const float* __restrict__ q0, const float* __restrict__ r0,
                            float* __restrict__ qsf, float* __restrict__ rsf,
                            __nv_bfloat16* qsh, __nv_bfloat16* qsl,
                            __nv_bfloat16* rsh, __nv_bfloat16* rsl,
                            __nv_bfloat16* xgh, __nv_bfloat16* xgl,
                            __nv_bfloat16* xqsh, __nv_bfloat16* xqsl,
                            __nv_bfloat16* xrsh, __nv_bfloat16* xrsl,
                            __nv_bfloat16* xplh, __nv_bfloat16* xpll,
                            __nv_bfloat16* xeh,  __nv_bfloat16* xel,
                            int* __restrict__ selrow, int* __restrict__ qmidx) {
    int i = blockIdx.x * 256 + threadIdx.x;
    int b = i >> 8, d = i & 255;
    int qm = (qmask[b * 2 + 1] > qmask[b * 2]) ? 1 : 0;
    if (d == 0) { qmidx[b] = qm; selrow[b] = b * 2 + qm; }
    float q = q0[(size_t)(b * 2 + qm) * DD + d];
    float r = r0[(size_t)(b * 2 + qm) * DD + d];
    float u = U[i];
    qsf[i] = q; rsf[i] = r;
    bsplit(q, qsh, qsl, i);
    bsplit(r, rsh, rsl, i);
    size_t o = (size_t)b * 768 + d;
    bsplit(q, xgh, xgl, o);
    bsplit(r, xgh, xgl, o + 256);
    bsplit(u, xgh, xgl, o + 512);
    size_t o2 = (size_t)b * 512 + 256 + d;
    bsplit(u, xqsh, xqsl, o2);
    bsplit(u, xrsh, xrsl, o2);
    bsplit(u, xplh, xpll, o2);
    bsplit(u, xeh, xel, o);
}

// ================= attention =================
__global__ void att_kernel(const float* __restrict__ gh, const float* __restrict__ attw,
                           __nv_bfloat16* __restrict__ xrsh, __nv_bfloat16* __restrict__ xrsl,
                           float* __restrict__ alpha_out) {
    extern __shared__ float sh[];
    __shared__ float s_aw[DD];
    __shared__ float s_scale[TT];
    __shared__ float s_alpha[TT];
    int b = blockIdx.x, tid = threadIdx.x;
    s_aw[tid] = attw[tid];
    for (int t = 0; t < TT; t++)
        sh[t * DD + tid] = gh[((size_t)t * BB + b) * DD + tid];
    __syncthreads();
    int w = tid >> 5, lane = tid & 31;
    for (int t = w; t < TT; t += 8) {
        float s = 0.f;
        #pragma unroll
        for (int i = 0; i < 8; i++) s += sh[t * DD + lane + i * 32] * s_aw[lane + i * 32];
        #pragma unroll
        for (int o = 16; o > 0; o >>= 1) s += __shfl_down_sync(0xffffffffu, s, o);
        if (lane == 0) s_scale[t] = s;
    }
    __syncthreads();
    if (w == 0) {
        float v0 = s_scale[lane], v1 = s_scale[lane + 32];
        float m = fmaxf(v0, v1);
        #pragma unroll
        for (int o = 16; o > 0; o >>= 1) m = fmaxf(m, __shfl_xor_sync(0xffffffffu, m, o));
        float e0 = expf(v0 - m), e1 = expf(v1 - m);
        float s = e0 + e1;
        #pragma unroll
        for (int o = 16; o > 0; o >>= 1) s += __shfl_xor_sync(0xffffffffu, s, o);
        float inv = 1.f / s;
        s_alpha[lane] = e0 * inv;
        s_alpha[lane + 32] = e1 * inv;
        alpha_out[(size_t)b * TT + lane] = e0 * inv;
        alpha_out[(size_t)b * TT + lane + 32] = e1 * inv;
    }
    __syncthreads();
    float acc = 0.f;
    for (int t = 0; t < TT; t++) acc += s_alpha[t] * sh[t * DD + tid];
    bsplit(acc, xrsh, xrsl, (size_t)b * 512 + tid);
}

// ================= fused GRU — m32n16 warp tile, 3-stage K=16 pipeline =================
// Block tile: 64 rows x 64 out-cols; 8 warps = 2(m) x 4(n); warp tile 32x16.
// Stage (K=16): 8 regions x (64 rows x 48B) = 8 x 3072 = 24576 B. 3 stages = 73728 B.
// Row stride 48 B (32 B payload + 16 B pad) keeps every 16B cp.async dest aligned;
// 48*r mod 128 distinct over 8 rows -> LDSM conflict-free.
// Regions: [A-hi | A-lo | W0h | W0l | W1h | W1l | W2h | W2l].
// Pipeline: prefetch 2 ahead, cp.async.wait_group 1, one barrier per stage.
#define RTILE 3072
#define STAGE_SB 24576
#define NSTG 3
#define GRU_SMEM (NSTG * STAGE_SB)

#define GATE2(ACCP, AF, BR) do { \
    mma16816((ACCP),     (AF), (BR)[0], (BR)[1]); \
    mma16816((ACCP) + 4, (AF), (BR)[2], (BR)[3]); \
} while (0)

__global__ __launch_bounds__(256, 2) void gru_mma_kernel(
    const __nv_bfloat16* __restrict__ Xhi, const __nv_bfloat16* __restrict__ Xlo,
    int K, int xshift,
    const __nv_bfloat16* __restrict__ Hhi, const __nv_bfloat16* __restrict__ Hlo,
    const float* __restrict__ Hf,
    const __nv_bfloat16* __restrict__ Wih_hi, const __nv_bfloat16* __restrict__ Wih_lo,
    const __nv_bfloat16* __restrict__ Whh_hi, const __nv_bfloat16* __restrict__ Whh_lo,
    const float* __restrict__ bih, const float* __restrict__ bhh,
    float* __restrict__ Out, const int* __restrict__ out_rows,
    const int* __restrict__ selrow, int zero_other,
    __nv_bfloat16* __restrict__ x1h, __nv_bfloat16* __restrict__ x1l,
    int x1_stride, int x1_off, int x1_sel,
    __nv_bfloat16* __restrict__ x2h, __nv_bfloat16* __restrict__ x2l,
    int x2_stride, int x2_off)
{
    extern __shared__ __align__(16) char dsm[];
    const uint32_t smb = smem_u32(dsm);

    const int tid = threadIdx.x;
    const int wid = tid >> 5, lane = tid & 31;
    const int warp_m = wid & 1, warp_n = wid >> 1;   // 2 m-warps x 4 n-warps
    const int row0 = blockIdx.x * 64, c0 = blockIdx.y * 64;

    const int nch0 = K / 16;           // input-GEMM stages
    const int ntot = nch0 + 16;        // + hidden-GEMM stages (256/16)

    float a0[16] = {}, a1[16] = {}, a2[16] = {}, a3[16] = {};

    // ---- loader setup: 4 vectors/thread/stage ----
    // vec id v = tid + 256*j; region = v>>7 (0..7); r = v&127; row = r>>1; half = r&1
    uint32_t sOff[4];
    const __nv_bfloat16* gp[4];
    int greg[4], grow[4], gcole[4];
    #pragma unroll
    for (int j = 0; j < 4; j++) {
        int v = tid + 256 * j;
        int region = v >> 7, r = v & 127;
        int row = r >> 1, cole = (r & 1) * 8;    // element col (8 bf16 per vec)
        sOff[j] = (uint32_t)region * RTILE + (uint32_t)row * 48 + (r & 1) * 16;
        greg[j] = region; grow[j] = row; gcole[j] = cole;
        if (region == 0)
            gp[j] = Xhi + (size_t)((row0 + row) >> xshift) * K + cole;
        else if (region == 1)
            gp[j] = Xlo + (size_t)((row0 + row) >> xshift) * K + cole;
        else {
            int g = (region - 2) >> 1, hl = region & 1;
            gp[j] = (hl ? Wih_lo : Wih_hi) + (size_t)(g * 256 + c0 + row) * K + cole;
        }
    }

    // ---- ldsm lane offsets (relative to stage base) ----
    const uint32_t AOFF = ((uint32_t)(warp_m * 32 + (lane & 7) + ((lane >> 3) & 1) * 8)) * 48
                        + (uint32_t)(lane >> 4) * 16;
    const uint32_t BOFF = 2 * RTILE
                        + ((uint32_t)(warp_n * 16 + (lane & 7) + (lane >> 4) * 8)) * 48
                        + (uint32_t)((lane >> 3) & 1) * 16;

    #define PREF(SOFF) do { \
        cp16(smb + (SOFF) + sOff[0], gp[0]); \
        cp16(smb + (SOFF) + sOff[1], gp[1]); \
        cp16(smb + (SOFF) + sOff[2], gp[2]); \
        cp16(smb + (SOFF) + sOff[3], gp[3]); \
        gp[0] += 16; gp[1] += 16; gp[2] += 16; gp[3] += 16; \
    } while (0)

    PREF(0);
    asm volatile("cp.async.commit_group;");
    PREF(STAGE_SB);
    asm volatile("cp.async.commit_group;");

    uint32_t stg_cons = 0;                 // consuming stage offset
    uint32_t stg_pref = 2 * STAGE_SB;      // next prefetch stage offset

    #pragma unroll 1
    for (int i = 0; i < ntot; i++) {
        asm volatile("cp.async.wait_group 1;");
        __syncthreads();    // stage i ready; stage being overwritten fully consumed

        if (i + 2 < ntot) {
            if (i + 2 == nch0) {    // switch sources to hidden GEMM
                #pragma unroll
                for (int j = 0; j < 4; j++) {
                    if (greg[j] == 0)
                        gp[j] = Hhi + (size_t)(row0 + grow[j]) * 256 + gcole[j];
                    else if (greg[j] == 1)
                        gp[j] = Hlo + (size_t)(row0 + grow[j]) * 256 + gcole[j];
                    else {
                        int g = (greg[j] - 2) >> 1, hl = greg[j] & 1;
                        gp[j] = (hl ? Whh_lo : Whh_hi)
                              + (size_t)(g * 256 + c0 + grow[j]) * 256 + gcole[j];
                    }
                }
            }
            PREF(stg_pref);
            stg_pref += STAGE_SB; if (stg_pref == NSTG * STAGE_SB) stg_pref = 0;
        }
        asm volatile("cp.async.commit_group;");

        const uint32_t base = smb + stg_cons;
        stg_cons += STAGE_SB; if (stg_cons == NSTG * STAGE_SB) stg_cons = 0;

        uint32_t ah0[4], ah1[4], al0[4], al1[4], bh[4], bl[4];
        ldsm4(ah0, base + AOFF);
        ldsm4(ah1, base + AOFF + 768);            // +16 rows (16*48)
        ldsm4(al0, base + AOFF + RTILE);
        ldsm4(al1, base + AOFF + RTILE + 768);
        // gate 0 -> a0
        ldsm4(bh, base + BOFF);
        ldsm4(bl, base + BOFF + RTILE);
        GATE2(a0,     ah0, bh); GATE2(a0 + 8, ah1, bh);
        GATE2(a0,     ah0, bl); GATE2(a0 + 8, ah1, bl);
        GATE2(a0,     al0, bh); GATE2(a0 + 8, al1, bh);
        // gate 1 -> a1
        ldsm4(bh, base + BOFF + 2 * RTILE);
        ldsm4(bl, base + BOFF + 3 * RTILE);
        GATE2(a1,     ah0, bh); GATE2(a1 + 8, ah1, bh);
        GATE2(a1,     ah0, bl); GATE2(a1 + 8, ah1, bl);
        GATE2(a1,     al0, bh); GATE2(a1 + 8, al1, bh);
        // gate 2 -> a2 (phase 0) or a3 (phase 1)
        ldsm4(bh, base + BOFF + 4 * RTILE);
        ldsm4(bl, base + BOFF + 5 * RTILE);
        if (i < nch0) {
            GATE2(a2,     ah0, bh); GATE2(a2 + 8, ah1, bh);
            GATE2(a2,     ah0, bl); GATE2(a2 + 8, ah1, bl);
            GATE2(a2,     al0, bh); GATE2(a2 + 8, al1, bh);
        } else {
            GATE2(a3,     ah0, bh); GATE2(a3 + 8, ah1, bh);
            GATE2(a3,     ah0, bl); GATE2(a3 + 8, ah1, bl);
            GATE2(a3,     al0, bh); GATE2(a3 + 8, al1, bh);
        }
    }
    #undef PREF

    // ---- epilogue ----
    #pragma unroll
    for (int msub = 0; msub < 2; msub++) {
        const int mrowb = row0 + warp_m * 32 + msub * 16 + (lane >> 2);
        #pragma unroll
        for (int half = 0; half < 2; half++) {
            int m = mrowb + half * 8;
            int orow = out_rows ? out_rows[m] : m;
            const float* hrow = Hf + (size_t)m * 256;
            float* op = Out + (size_t)orow * 256;
            float* oo = zero_other ? (Out + (size_t)(orow ^ 1) * 256) : nullptr;
            int x1b = x1_sel ? (m >> 1) : m;
            bool x1ok = x1h && (!x1_sel || (selrow[x1b] == m));
            #pragma unroll
            for (int nt = 0; nt < 2; nt++) {
                #pragma unroll
                for (int e = 0; e < 2; e++) {
                    int col = c0 + warp_n * 16 + (lane & 3) * 2 + nt * 8 + e;
                    int d = msub * 8 + nt * 4 + half * 2 + e;
                    float ar = a0[d] + bih[col] + bhh[col];
                    float az = a1[d] + bih[256 + col] + bhh[256 + col];
                    float r = 1.f / (1.f + expf(-ar));
                    float z = 1.f / (1.f + expf(-az));
                    float n = tanhf(a2[d] + bih[512 + col] + r * (a3[d] + bhh[512 + col]));
                    float v = (1.f - z) * n + z * hrow[col];
                    op[col] = v;
                    if (oo) oo[col] = 0.f;
                    if (x1ok) bsplit(v, x1h, x1l, (size_t)x1b * x1_stride + x1_off + col);
                    if (x2h)  bsplit(v, x2h, x2l, (size_t)m * x2_stride + x2_off + col);
                }
            }
        }
    }
}

// ================= launch =================
extern "C" void kernel_launch(void* const* d_in, const int* in_sizes, int n_in,
                              void* d_out, int out_size) {
    const float* U      = (const float*)d_in[0];
    const float* qmask  = (const float*)d_in[1];
    const float* g_hist = (const float*)d_in[2];
    const float* q0     = (const float*)d_in[3];
    const float* r0     = (const float*)d_in[4];
    const float* e0     = (const float*)d_in[5];
    const float* g_wih  = (const float*)d_in[6];
    const float* g_whh  = (const float*)d_in[7];
    const float* g_bih  = (const float*)d_in[8];
    const float* g_bhh  = (const float*)d_in[9];
    const float* p_wih  = (const float*)d_in[10];
    const float* p_whh  = (const float*)d_in[11];
    const float* p_bih  = (const float*)d_in[12];
    const float* p_bhh  = (const float*)d_in[13];
    const float* pl_wih = (const float*)d_in[14];
    const float* pl_whh = (const float*)d_in[15];
    const float* pl_bih = (const float*)d_in[16];
    const float* pl_bhh = (const float*)d_in[17];
    const float* r_wih  = (const float*)d_in[18];
    const float* r_whh  = (const float*)d_in[19];
    const float* r_bih  = (const float*)d_in[20];
    const float* r_bhh  = (const float*)d_in[21];
    const float* e_wih  = (const float*)d_in[22];
    const float* e_whh  = (const float*)d_in[23];
    const float* e_bih  = (const float*)d_in[24];
    const float* e_bhh  = (const float*)d_in[25];
    const float* att_w  = (const float*)d_in[26];

    float* out = (float*)d_out;
    float* o_g = out;
    float* o_q = out + 1048576;
    float* o_r = out + 3145728;
    float* o_e = out + 5242880;
    float* o_a = out + 6291456;

    void* poolv;
    cudaGetSymbolAddress(&poolv, g_pool);
    char* pool = (char*)poolv;
    #define BF(off) ((__nv_bfloat16*)(pool + (off)))
    #define FP(off) ((float*)(pool + (off)))
    int* selrow = (int*)(pool + O_SELROW);
    int* qmidx  = (int*)(pool + O_QMIDX);

    cudaFuncSetAttribute(att_kernel, cudaFuncAttributeMaxDynamicSharedMemorySize,
                         TT * DD * (int)sizeof(float));
    cudaFuncSetAttribute(gru_mma_kernel, cudaFuncAttributeMaxDynamicSharedMemorySize, GRU_SMEM);

    const float* ghl = g_hist + (size_t)63 * BB * DD;

    // 1) conversions
    ConvTable ct;
    int ti = 0, total_blk = 0;
    auto addseg = [&](const float* s, size_t oh, size_t ol, int n) {
        ct.s[ti].src = s; ct.s[ti].hi = BF(oh); ct.s[ti].lo = BF(ol);
        ct.s[ti].nblk = n / 1024; total_blk += n / 1024; ti++;
    };
    addseg(g_wih,  O_WGIH_H, O_WGIH_L, 768 * 768);
    addseg(g_whh,  O_WGHH_H, O_WGHH_L, 768 * 256);
    addseg(p_wih,  O_WPIH_H, O_WPIH_L, 768 * 512);
    addseg(p_whh,  O_WPHH_H, O_WPHH_L, 768 * 256);
    addseg(pl_wih, O_WLIH_H, O_WLIH_L, 768 * 512);
    addseg(pl_whh, O_WLHH_H, O_WLHH_L, 768 * 256);
    addseg(r_wih,  O_WRIH_H, O_WRIH_L, 768 * 512);
    addseg(r_whh,  O_WRHH_H, O_WRHH_L, 768 * 256);
    addseg(e_wih,  O_WEIH_H, O_WEIH_L, 768 * 768);
    addseg(e_whh,  O_WEHH_H, O_WEHH_L, 768 * 256);
    addseg(q0,     O_Q0_H,   O_Q0_L,   2 * BB * 256);
    addseg(ghl,    O_GH_H,   O_GH_L,   BB * 256);
    addseg(e0,     O_E0_H,   O_E0_L,   BB * 256);
    conv_all_kernel<<<total_blk, 256>>>(ct);

    // 2) prep
    prep_kernel<<<BB, 256>>>(U, qmask, q0, r0,
        FP(O_QSF), FP(O_RSF), BF(O_QS_H), BF(O_QS_L), BF(O_RS_H), BF(O_RS_L),
        BF(O_XG_H), BF(O_XG_L),
        BF(O_XQS_H), BF(O_XQS_L), BF(O_XRS_H), BF(O_XRS_L),
        BF(O_XPL_H), BF(O_XPL_L), BF(O_XE_H), BF(O_XE_L),
        selrow, qmidx);

    // 3) attention -> xrs first half + alpha
    att_kernel<<<BB, 256, TT * DD * sizeof(float)>>>(g_hist, att_w,
        BF(O_XRS_H), BF(O_XRS_L), o_a);

    // 4) g GRU: K=768; epilogue writes xqs[0:256] and xe[512:768]
    gru_mma_kernel<<<dim3(BB / 64, 4), 256, GRU_SMEM>>>(
        BF(O_XG_H), BF(O_XG_L), 768, 0,
        BF(O_GH_H), BF(O_GH_L), ghl,
        BF(O_WGIH_H), BF(O_WGIH_L), BF(O_WGHH_H), BF(O_WGHH_L),
        g_bih, g_bhh, o_g, nullptr,
        nullptr, 0,
        BF(O_XQS_H), BF(O_XQS_L), 512, 0, 0,
        BF(O_XE_H), BF(O_XE_L), 768, 512);

    // 5) qs GRU: 8192 rows; epilogue writes xpl[0:256] for selected rows
    gru_mma_kernel<<<dim3(2 * BB / 64, 4), 256, GRU_SMEM>>>(
        BF(O_XQS_H), BF(O_XQS_L), 512, 1,
        BF(O_Q0_H), BF(O_Q0_L), q0,
        BF(O_WPIH_H), BF(O_WPIH_L), BF(O_WPHH_H), BF(O_WPHH_L),
        p_bih, p_bhh, o_q, nullptr,
        selrow, 0,
        BF(O_XPL_H), BF(O_XPL_L), 512, 0, 1,
        nullptr, nullptr, 0, 0);

    // 6) rs GRU: selected rows, scatter + zero sibling row   [ncu slot 6]
    gru_mma_kernel<<<dim3(BB / 64, 4), 256, GRU_SMEM>>>(
        BF(O_XRS_H), BF(O_XRS_L), 512, 0,
        BF(O_RS_H), BF(O_RS_L), FP(O_RSF),
        BF(O_WRIH_H), BF(O_WRIH_L), BF(O_WRHH_H), BF(O_WRHH_L),
        r_bih, r_bhh, o_r, selrow,
        nullptr, 1,
        nullptr, nullptr, 0, 0, 0,
        nullptr, nullptr, 0, 0);

    // 7) ql GRU: selected rows, scatter into q_; epilogue writes xe[256:512]
    gru_mma_kernel<<<dim3(BB / 64, 4), 256, GRU_SMEM>>>(
        BF(O_XPL_H), BF(O_XPL_L), 512, 0,
        BF(O_QS_H), BF(O_QS_L), FP(O_QSF),
        BF(O_WLIH_H), BF(O_WLIH_L), BF(O_WLHH_H), BF(O_WLHH_L),
        pl_bih, pl_bhh, o_q, selrow,
        nullptr, 0,
        BF(O_XE_H), BF(O_XE_L), 768, 256, 0,
        nullptr, nullptr, 0, 0);

    // 8) e GRU: K=768
    gru_mma_kernel<<<dim3(BB / 64, 4), 256, GRU_SMEM>>>(
        BF(O_XE_H), BF(O_XE_L), 768, 0,
        BF(O_E0_H), BF(O_E0_L), e0,
        BF(O_WEIH_H), BF(O_WEIH_L), BF(O_WEHH_H), BF(O_WEHH_L),
        e_bih, e_bhh, o_e, nullptr,
        nullptr, 0,
        nullptr, nullptr, 0, 0, 0,
        nullptr, nullptr, 0, 0);
    #undef BF
    #undef FP
}

// round 14
// speedup vs baseline: 1.2349x; 1.2349x over previous
#include <cuda_runtime.h>
#include <cuda_fp16.h>
#include <math.h>
#include <stdint.h>

#define BB 4096
#define DD 256
#define TT 64

// ================= PTX helpers (baseline ISA only) =================
__device__ __forceinline__ uint32_t smem_u32(const void* p) {
    uint32_t a;
    asm("{ .reg .u64 t; cvta.to.shared.u64 t, %1; cvt.u32.u64 %0, t; }" : "=r"(a) : "l"(p));
    return a;
}
__device__ __forceinline__ void cp16(uint32_t saddr, const void* g) {
    asm volatile("cp.async.cg.shared.global [%0], [%1], 16;" :: "r"(saddr), "l"(g));
}
__device__ __forceinline__ void ldsm4(uint32_t* r, uint32_t addr) {
    asm volatile("ldmatrix.sync.aligned.m8n8.x4.shared.b16 {%0,%1,%2,%3}, [%4];"
        : "=r"(r[0]), "=r"(r[1]), "=r"(r[2]), "=r"(r[3]) : "r"(addr));
}
__device__ __forceinline__ void mma16816(float* c, const uint32_t* a, uint32_t b0, uint32_t b1) {
    asm volatile("mma.sync.aligned.m16n8k16.row.col.f32.f16.f16.f32 "
        "{%0,%1,%2,%3}, {%4,%5,%6,%7}, {%8,%9}, {%0,%1,%2,%3};"
        : "+f"(c[0]), "+f"(c[1]), "+f"(c[2]), "+f"(c[3])
        : "r"(a[0]), "r"(a[1]), "r"(a[2]), "r"(a[3]), "r"(b0), "r"(b1));
}

// ================= scratch pool =================
static constexpr size_t SZ_XG  = (size_t)BB * 768 * 2;
static constexpr size_t SZ_XS  = (size_t)BB * 512 * 2;
static constexpr size_t SZ_BD  = (size_t)BB * 256 * 2;
static constexpr size_t SZ_Q0  = (size_t)2 * BB * 256 * 2;
static constexpr size_t SZ_BDF = (size_t)BB * 256 * 4;

static constexpr size_t O_XG   = 0;
static constexpr size_t O_XE   = O_XG  + SZ_XG;
static constexpr size_t O_XQS  = O_XE  + SZ_XG;
static constexpr size_t O_XRS  = O_XQS + SZ_XS;
static constexpr size_t O_XPL  = O_XRS + SZ_XS;
static constexpr size_t O_Q0H  = O_XPL + SZ_XS;
static constexpr size_t O_GHH  = O_Q0H + SZ_Q0;
static constexpr size_t O_E0H  = O_GHH + SZ_BD;
static constexpr size_t O_QSH  = O_E0H + SZ_BD;   // q0sel fp16
static constexpr size_t O_RSH  = O_QSH + SZ_BD;   // r0sel fp16
static constexpr size_t O_QSF  = O_RSH + SZ_BD;   // q0sel f32
static constexpr size_t O_RSF  = O_QSF + SZ_BDF;
static constexpr size_t SZ_W768 = (size_t)768 * 768 * 2;
static constexpr size_t SZ_W512 = (size_t)768 * 512 * 2;
static constexpr size_t SZ_W256 = (size_t)768 * 256 * 2;
static constexpr size_t O_WGIH_H = O_RSF + SZ_BDF;
static constexpr size_t O_WGIH_L = O_WGIH_H + SZ_W768;
static constexpr size_t O_WGHH_H = O_WGIH_L + SZ_W768;
static constexpr size_t O_WGHH_L = O_WGHH_H + SZ_W256;
static constexpr size_t O_WPIH_H = O_WGHH_L + SZ_W256;
static constexpr size_t O_WPIH_L = O_WPIH_H + SZ_W512;
static constexpr size_t O_WPHH_H = O_WPIH_L + SZ_W512;
static constexpr size_t O_WPHH_L = O_WPHH_H + SZ_W256;
static constexpr size_t O_WLIH_H = O_WPHH_L + SZ_W256;
static constexpr size_t O_WLIH_L = O_WLIH_H + SZ_W512;
static constexpr size_t O_WLHH_H = O_WLIH_L + SZ_W512;
static constexpr size_t O_WLHH_L = O_WLHH_H + SZ_W256;
static constexpr size_t O_WRIH_H = O_WLHH_L + SZ_W256;
static constexpr size_t O_WRIH_L = O_WRIH_H + SZ_W512;
static constexpr size_t O_WRHH_H = O_WRIH_L + SZ_W512;
static constexpr size_t O_WRHH_L = O_WRHH_H + SZ_W256;
static constexpr size_t O_WEIH_H = O_WRHH_L + SZ_W256;
static constexpr size_t O_WEIH_L = O_WEIH_H + SZ_W768;
static constexpr size_t O_WEHH_H = O_WEIH_L + SZ_W768;
static constexpr size_t O_WEHH_L = O_WEHH_H + SZ_W256;
static constexpr size_t O_SELROW = O_WEHH_L + SZ_W256;
static constexpr size_t O_QMIDX  = O_SELROW + BB * 4;
static constexpr size_t POOL_SZ  = O_QMIDX + BB * 4;

__device__ __align__(1024) unsigned char g_pool[POOL_SZ];

// ================= conv_all: weights -> fp16 hi+lo; activations -> fp16 hi only ====
struct ConvSeg { const float* src; __half* hi; __half* lo; int nblk; };
struct ConvTable { ConvSeg s[13]; };

__global__ void conv_all_kernel(ConvTable t) {
    int blk = blockIdx.x;
    #pragma unroll 1
    for (int i = 0; i < 13; i++) {
        int nb = t.s[i].nblk;
        if (blk < nb) {
            int idx = blk * 1024 + threadIdx.x * 4;
            float4 v = *(const float4*)(t.s[i].src + idx);
            __half h0 = __float2half(v.x);
            __half h1 = __float2half(v.y);
            __half h2 = __float2half(v.z);
            __half h3 = __float2half(v.w);
            __half2 hv0, hv1;
            hv0.x = h0; hv0.y = h1; hv1.x = h2; hv1.y = h3;
            *(__half2*)(t.s[i].hi + idx)     = hv0;
            *(__half2*)(t.s[i].hi + idx + 2) = hv1;
            if (t.s[i].lo) {
                __half2 lv0, lv1;
                lv0.x = __float2half(v.x - __half2float(h0));
                lv0.y = __float2half(v.y - __half2float(h1));
                lv1.x = __float2half(v.z - __half2float(h2));
                lv1.y = __float2half(v.w - __half2float(h3));
                *(__half2*)(t.s[i].lo + idx)     = lv0;
                *(__half2*)(t.s[i].lo + idx + 2) = lv1;
            }
            return;
        }
        blk -= nb;
    }
}

// ================= prep =================
__global__ void prep_kernel(const float* __restrict__ U, const float* __restrict__ qmask,
                            const float* __restrict__ q0, const float* __restrict__ r0,
                            float* __restrict__ qsf, float* __restrict__ rsf,
                            __half* qsh, __half* rsh,
                            __half* xg, __half* xqs, __half* xrs, __half* xpl, __half* xe,
                            int* __restrict__ selrow, int* __restrict__ qmidx) {
    int i = blockIdx.x * 256 + threadIdx.x;
    int b = i >> 8, d = i & 255;
    int qm = (qmask[b * 2 + 1] > qmask[b * 2]) ? 1 : 0;
    if (d == 0) { qmidx[b] = qm; selrow[b] = b * 2 + qm; }
    float q = q0[(size_t)(b * 2 + qm) * DD + d];
    float r = r0[(size_t)(b * 2 + qm) * DD + d];
    float u = U[i];
    qsf[i] = q; rsf[i] = r;
    qsh[i] = __float2half(q);
    rsh[i] = __float2half(r);
    size_t o = (size_t)b * 768 + d;
    xg[o]       = __float2half(q);
    xg[o + 256] = __float2half(r);
    xg[o + 512] = __float2half(u);
    size_t o2 = (size_t)b * 512 + 256 + d;
    __half uh = __float2half(u);
    xqs[o2] = uh;
    xrs[o2] = uh;
    xpl[o2] = uh;
    xe[o]   = uh;   // xe seg0 = U
}

// ================= attention =================
__global__ void att_kernel(const float* __restrict__ gh, const float* __restrict__ attw,
                           __half* __restrict__ xrs, float* __restrict__ alpha_out) {
    extern __shared__ float sh[];
    __shared__ float s_aw[DD];
    __shared__ float s_scale[TT];
    __shared__ float s_alpha[TT];
    int b = blockIdx.x, tid = threadIdx.x;
    s_aw[tid] = attw[tid];
    for (int t = 0; t < TT; t++)
        sh[t * DD + tid] = gh[((size_t)t * BB + b) * DD + tid];
    __syncthreads();
    int w = tid >> 5, lane = tid & 31;
    for (int t = w; t < TT; t += 8) {
        float s = 0.f;
        #pragma unroll
        for (int i = 0; i < 8; i++) s += sh[t * DD + lane + i * 32] * s_aw[lane + i * 32];
        #pragma unroll
        for (int o = 16; o > 0; o >>= 1) s += __shfl_down_sync(0xffffffffu, s, o);
        if (lane == 0) s_scale[t] = s;
    }
    __syncthreads();
    if (w == 0) {
        float v0 = s_scale[lane], v1 = s_scale[lane + 32];
        float m = fmaxf(v0, v1);
        #pragma unroll
        for (int o = 16; o > 0; o >>= 1) m = fmaxf(m, __shfl_xor_sync(0xffffffffu, m, o));
        float e0 = expf(v0 - m), e1 = expf(v1 - m);
        float s = e0 + e1;
        #pragma unroll
        for (int o = 16; o > 0; o >>= 1) s += __shfl_xor_sync(0xffffffffu, s, o);
        float inv = 1.f / s;
        s_alpha[lane] = e0 * inv;
        s_alpha[lane + 32] = e1 * inv;
        alpha_out[(size_t)b * TT + lane] = e0 * inv;
        alpha_out[(size_t)b * TT + lane + 32] = e1 * inv;
    }
    __syncthreads();
    float acc = 0.f;
    for (int t = 0; t < TT; t++) acc += s_alpha[t] * sh[t * DD + tid];
    xrs[(size_t)b * 512 + tid] = __float2half(acc);
}

// ================= fused GRU — fp16 2-term split, m32n16 warp tile =================
// A·W ≈ A_fp16·(W_hi + W_lo)  (weights split; activations quantized once).
// Block tile: 64 rows x 64 out-cols; 8 warps = 2(m) x 4(n); warp tile 32x16.
// Stage (K=32): A(5120) + W[6 x 5120] = 35840 B. Double buffer = 71680 B.
// Per k16: 2 A-LDSM + 6 B-LDSM, 24 MMAs. One barrier per chunk (R10/R11 scheme).
#define ATILE 5120
#define WREG  5120
#define WTILE 5120
#define STAGE_SB 35840
#define GRU_SMEM (2 * STAGE_SB)

#define GATE2(ACCP, AF, BR) do { \
    mma16816((ACCP),     (AF), (BR)[0], (BR)[1]); \
    mma16816((ACCP) + 4, (AF), (BR)[2], (BR)[3]); \
} while (0)

__global__ __launch_bounds__(256, 2) void gru_mma_kernel(
    const __half* __restrict__ X, int K, int xshift,
    const __half* __restrict__ H, const float* __restrict__ Hf,
    const __half* __restrict__ Wih_hi, const __half* __restrict__ Wih_lo,
    const __half* __restrict__ Whh_hi, const __half* __restrict__ Whh_lo,
    const float* __restrict__ bih, const float* __restrict__ bhh,
    float* __restrict__ Out, const int* __restrict__ out_rows,
    const int* __restrict__ selrow, int zero_other,
    __half* __restrict__ x1, int x1_stride, int x1_off, int x1_sel,
    __half* __restrict__ x2, int x2_stride, int x2_off)
{
    extern __shared__ __align__(16) char dsm[];
    const uint32_t smb = smem_u32(dsm);

    const int tid = threadIdx.x;
    const int wid = tid >> 5, lane = tid & 31;
    const int warp_m = wid & 1, warp_n = wid >> 1;   // 2 m-warps x 4 n-warps
    const int row0 = blockIdx.x * 64, c0 = blockIdx.y * 64;

    const int nch0 = K / 32;
    const int ntot = nch0 + 8;

    float a0[16] = {}, a1[16] = {}, a2[16] = {}, a3[16] = {};

    // ---- loader setup: 7 vectors/thread/chunk (1 A + 6 W) ----
    const int lr = tid >> 2, lcv = tid & 3;
    const uint32_t sA = (uint32_t)lr * 80 + lcv * 16;
    uint32_t sW[6];
    int wgi[6], whl[6], wri[6], wci[6];
    #pragma unroll
    for (int j = 0; j < 6; j++) {
        int v = tid + 256 * j;           // 0..1535
        int rrow = v >> 2, c = v & 3;    // region row 0..383
        int tile = rrow >> 6;            // 0..5
        sW[j] = WREG + (uint32_t)tile * WTILE + (uint32_t)(rrow & 63) * 80 + c * 16;
        wgi[j] = tile >> 1; whl[j] = tile & 1; wri[j] = rrow & 63; wci[j] = c;
    }
    const __half* pa = X + (size_t)((row0 + lr) >> xshift) * K + lcv * 8;
    const __half* pw[6];
    #pragma unroll
    for (int j = 0; j < 6; j++)
        pw[j] = (whl[j] ? Wih_lo : Wih_hi)
              + (size_t)(wgi[j] * 256 + c0 + wri[j]) * K + wci[j] * 8;

    // ---- ldsm lane offsets (relative to stage base) ----
    const uint32_t AOFF = ((uint32_t)(warp_m * 32 + (lane & 7) + ((lane >> 3) & 1) * 8)) * 80
                        + (uint32_t)(lane >> 4) * 16;
    const uint32_t BOFF = WREG
                        + ((uint32_t)(warp_n * 16 + (lane & 7) + (lane >> 4) * 8)) * 80
                        + (uint32_t)((lane >> 3) & 1) * 16;

    #define PREF(SOFF) do { \
        cp16(smb + (SOFF) + sA,    pa); \
        cp16(smb + (SOFF) + sW[0], pw[0]); \
        cp16(smb + (SOFF) + sW[1], pw[1]); \
        cp16(smb + (SOFF) + sW[2], pw[2]); \
        cp16(smb + (SOFF) + sW[3], pw[3]); \
        cp16(smb + (SOFF) + sW[4], pw[4]); \
        cp16(smb + (SOFF) + sW[5], pw[5]); \
        pa += 32; \
        pw[0] += 32; pw[1] += 32; pw[2] += 32; \
        pw[3] += 32; pw[4] += 32; pw[5] += 32; \
    } while (0)

    PREF(0);
    asm volatile("cp.async.commit_group;");

    #pragma unroll 1
    for (int i = 0; i < ntot; i++) {
        asm volatile("cp.async.wait_group 0;");
        __syncthreads();   // publish stage i; certify other stage consumed

        if (i + 1 < ntot) {
            if (i + 1 == nch0) {
                pa = H + (size_t)(row0 + lr) * 256 + lcv * 8;
                #pragma unroll
                for (int j = 0; j < 6; j++)
                    pw[j] = (whl[j] ? Whh_lo : Whh_hi)
                          + (size_t)(wgi[j] * 256 + c0 + wri[j]) * 256 + wci[j] * 8;
            }
            PREF(((i + 1) & 1) ? STAGE_SB : 0u);
            asm volatile("cp.async.commit_group;");
        }

        const uint32_t base = smb + ((i & 1) ? STAGE_SB : 0u);
        #pragma unroll
        for (int s = 0; s < 2; s++) {
            const uint32_t ka = (uint32_t)s * 32;
            uint32_t ah0[4], ah1[4], bh[4], bl[4];
            ldsm4(ah0, base + AOFF + ka);
            ldsm4(ah1, base + AOFF + 1280 + ka);          // +16 rows
            // gate 0 -> a0
            ldsm4(bh, base + BOFF + ka);
            ldsm4(bl, base + BOFF + WTILE + ka);
            GATE2(a0,     ah0, bh); GATE2(a0 + 8, ah1, bh);
            GATE2(a0,     ah0, bl); GATE2(a0 + 8, ah1, bl);
            // gate 1 -> a1
            ldsm4(bh, base + BOFF + 2 * WTILE + ka);
            ldsm4(bl, base + BOFF + 3 * WTILE + ka);
            GATE2(a1,     ah0, bh); GATE2(a1 + 8, ah1, bh);
            GATE2(a1,     ah0, bl); GATE2(a1 + 8, ah1, bl);
            // gate 2 -> a2 (phase 0) or a3 (phase 1)
            ldsm4(bh, base + BOFF + 4 * WTILE + ka);
            ldsm4(bl, base + BOFF + 5 * WTILE + ka);
            if (i < nch0) {
                GATE2(a2,     ah0, bh); GATE2(a2 + 8, ah1, bh);
                GATE2(a2,     ah0, bl); GATE2(a2 + 8, ah1, bl);
            } else {
                GATE2(a3,     ah0, bh); GATE2(a3 + 8, ah1, bh);
                GATE2(a3,     ah0, bl); GATE2(a3 + 8, ah1, bl);
            }
        }
    }
    #undef PREF

    // ---- epilogue ----
    #pragma unroll
    for (int msub = 0; msub < 2; msub++) {
        const int mrowb = row0 + warp_m * 32 + msub * 16 + (lane >> 2);
        #pragma unroll
        for (int half = 0; half < 2; half++) {
            int m = mrowb + half * 8;
            int orow = out_rows ? out_rows[m] : m;
            const float* hrow = Hf + (size_t)m * 256;
            float* op = Out + (size_t)orow * 256;
            float* oo = zero_other ? (Out + (size_t)(orow ^ 1) * 256) : nullptr;
            int x1b = x1_sel ? (m >> 1) : m;
            bool x1ok = x1 && (!x1_sel || (selrow[x1b] == m));
            #pragma unroll
            for (int nt = 0; nt < 2; nt++) {
                #pragma unroll
                for (int e = 0; e < 2; e++) {
                    int col = c0 + warp_n * 16 + (lane & 3) * 2 + nt * 8 + e;
                    int d = msub * 8 + nt * 4 + half * 2 + e;
                    float ar = a0[d] + bih[col] + bhh[col];
                    float az = a1[d] + bih[256 + col] + bhh[256 + col];
                    float r = 1.f / (1.f + expf(-ar));
                    float z = 1.f / (1.f + expf(-az));
                    float n = tanhf(a2[d] + bih[512 + col] + r * (a3[d] + bhh[512 + col]));
                    float v = (1.f - z) * n + z * hrow[col];
                    op[col] = v;
                    if (oo) oo[col] = 0.f;
                    if (x1ok) x1[(size_t)x1b * x1_stride + x1_off + col] = __float2half(v);
                    if (x2)   x2[(size_t)m * x2_stride + x2_off + col]   = __float2half(v);
                }
            }
        }
    }
}

// ================= launch =================
extern "C" void kernel_launch(void* const* d_in, const int* in_sizes, int n_in,
                              void* d_out, int out_size) {
    const float* U      = (const float*)d_in[0];
    const float* qmask  = (const float*)d_in[1];
    const float* g_hist = (const float*)d_in[2];
    const float* q0     = (const float*)d_in[3];
    const float* r0     = (const float*)d_in[4];
    const float* e0     = (const float*)d_in[5];
    const float* g_wih  = (const float*)d_in[6];
    const float* g_whh  = (const float*)d_in[7];
    const float* g_bih  = (const float*)d_in[8];
    const float* g_bhh  = (const float*)d_in[9];
    const float* p_wih  = (const float*)d_in[10];
    const float* p_whh  = (const float*)d_in[11];
    const float* p_bih  = (const float*)d_in[12];
    const float* p_bhh  = (const float*)d_in[13];
    const float* pl_wih = (const float*)d_in[14];
    const float* pl_whh = (const float*)d_in[15];
    const float* pl_bih = (const float*)d_in[16];
    const float* pl_bhh = (const float*)d_in[17];
    const float* r_wih  = (const float*)d_in[18];
    const float* r_whh  = (const float*)d_in[19];
    const float* r_bih  = (const float*)d_in[20];
    const float* r_bhh  = (const float*)d_in[21];
    const float* e_wih  = (const float*)d_in[22];
    const float* e_whh  = (const float*)d_in[23];
    const float* e_bih  = (const float*)d_in[24];
    const float* e_bhh  = (const float*)d_in[25];
    const float* att_w  = (const float*)d_in[26];

    float* out = (float*)d_out;
    float* o_g = out;
    float* o_q = out + 1048576;
    float* o_r = out + 3145728;
    float* o_e = out + 5242880;
    float* o_a = out + 6291456;

    void* poolv;
    cudaGetSymbolAddress(&poolv, g_pool);
    char* pool = (char*)poolv;
    #define HF(off) ((__half*)(pool + (off)))
    #define FP(off) ((float*)(pool + (off)))
    int* selrow = (int*)(pool + O_SELROW);
    int* qmidx  = (int*)(pool + O_QMIDX);

    cudaFuncSetAttribute(att_kernel, cudaFuncAttributeMaxDynamicSharedMemorySize,
                         TT * DD * (int)sizeof(float));
    cudaFuncSetAttribute(gru_mma_kernel, cudaFuncAttributeMaxDynamicSharedMemorySize, GRU_SMEM);

    const float* ghl = g_hist + (size_t)63 * BB * DD;

    // 1) conversions: weights hi+lo, activations hi only
    ConvTable ct;
    int ti = 0, total_blk = 0;
    auto addseg = [&](const float* s, size_t oh, size_t ol, int n) {
        ct.s[ti].src = s; ct.s[ti].hi = HF(oh);
        ct.s[ti].lo = ol ? HF(ol) : nullptr;
        ct.s[ti].nblk = n / 1024; total_blk += n / 1024; ti++;
    };
    addseg(g_wih,  O_WGIH_H, O_WGIH_L, 768 * 768);
    addseg(g_whh,  O_WGHH_H, O_WGHH_L, 768 * 256);
    addseg(p_wih,  O_WPIH_H, O_WPIH_L, 768 * 512);
    addseg(p_whh,  O_WPHH_H, O_WPHH_L, 768 * 256);
    addseg(pl_wih, O_WLIH_H, O_WLIH_L, 768 * 512);
    addseg(pl_whh, O_WLHH_H, O_WLHH_L, 768 * 256);
    addseg(r_wih,  O_WRIH_H, O_WRIH_L, 768 * 512);
    addseg(r_whh,  O_WRHH_H, O_WRHH_L, 768 * 256);
    addseg(e_wih,  O_WEIH_H, O_WEIH_L, 768 * 768);
    addseg(e_whh,  O_WEHH_H, O_WEHH_L, 768 * 256);
    addseg(q0,     O_Q0H,    0,        2 * BB * 256);
    addseg(ghl,    O_GHH,    0,        BB * 256);
    addseg(e0,     O_E0H,    0,        BB * 256);
    conv_all_kernel<<<total_blk, 256>>>(ct);

    // 2) prep
    prep_kernel<<<BB, 256>>>(U, qmask, q0, r0,
        FP(O_QSF), FP(O_RSF), HF(O_QSH), HF(O_RSH),
        HF(O_XG), HF(O_XQS), HF(O_XRS), HF(O_XPL), HF(O_XE),
        selrow, qmidx);

    // 3) attention -> xrs first half + alpha
    att_kernel<<<BB, 256, TT * DD * sizeof(float)>>>(g_hist, att_w, HF(O_XRS), o_a);

    // 4) g GRU: K=768; epilogue writes xqs[0:256] and xe[512:768]
    gru_mma_kernel<<<dim3(BB / 64, 4), 256, GRU_SMEM>>>(
        HF(O_XG), 768, 0,
        HF(O_GHH), ghl,
        HF(O_WGIH_H), HF(O_WGIH_L), HF(O_WGHH_H), HF(O_WGHH_L),
        g_bih, g_bhh, o_g, nullptr,
        nullptr, 0,
        HF(O_XQS), 512, 0, 0,
        HF(O_XE), 768, 512);

    // 5) qs GRU: 8192 rows; epilogue writes xpl[0:256] for selected rows
    gru_mma_kernel<<<dim3(2 * BB / 64, 4), 256, GRU_SMEM>>>(
        HF(O_XQS), 512, 1,
        HF(O_Q0H), q0,
        HF(O_WPIH_H), HF(O_WPIH_L), HF(O_WPHH_H), HF(O_WPHH_L),
        p_bih, p_bhh, o_q, nullptr,
        selrow, 0,
        HF(O_XPL), 512, 0, 1,
        nullptr, 0, 0);

    // 6) rs GRU: selected rows, scatter + zero sibling row   [ncu slot 6]
    gru_mma_kernel<<<dim3(BB / 64, 4), 256, GRU_SMEM>>>(
        HF(O_XRS), 512, 0,
        HF(O_RSH), FP(O_RSF),
        HF(O_WRIH_H), HF(O_WRIH_L), HF(O_WRHH_H), HF(O_WRHH_L),
        r_bih, r_bhh, o_r, selrow,
        nullptr, 1,
        nullptr, 0, 0, 0,
        nullptr, 0, 0);

    // 7) ql GRU: selected rows, scatter into q_; epilogue writes xe[256:512]
    gru_mma_kernel<<<dim3(BB / 64, 4), 256, GRU_SMEM>>>(
        HF(O_XPL), 512, 0,
        HF(O_QSH), FP(O_QSF),
        HF(O_WLIH_H), HF(O_WLIH_L), HF(O_WLHH_H), HF(O_WLHH_L),
        pl_bih, pl_bhh, o_q, selrow,
        nullptr, 0,
        HF(O_XE), 768, 256, 0,
        nullptr, 0, 0);

    // 8) e GRU: K=768
    gru_mma_kernel<<<dim3(BB / 64, 4), 256, GRU_SMEM>>>(
        HF(O_XE), 768, 0,
        HF(O_E0H), e0,
        HF(O_WEIH_H), HF(O_WEIH_L), HF(O_WEHH_H), HF(O_WEHH_L),
        e_bih, e_bhh, o_e, nullptr,
        nullptr, 0,
        nullptr, 0, 0, 0,
        nullptr, 0, 0);
    #undef HF
    #undef FP
}

// round 15
// speedup vs baseline: 1.7117x; 1.3861x over previous
#include <cuda_runtime.h>
#include <cuda_fp16.h>
#include <math.h>
#include <stdint.h>

#define BB 4096
#define DD 256
#define TT 64

// ================= PTX helpers (baseline ISA only) =================
__device__ __forceinline__ uint32_t smem_u32(const void* p) {
    uint32_t a;
    asm("{ .reg .u64 t; cvta.to.shared.u64 t, %1; cvt.u32.u64 %0, t; }" : "=r"(a) : "l"(p));
    return a;
}
__device__ __forceinline__ void cp16(uint32_t saddr, const void* g) {
    asm volatile("cp.async.cg.shared.global [%0], [%1], 16;" :: "r"(saddr), "l"(g));
}
__device__ __forceinline__ void ldsm4(uint32_t* r, uint32_t addr) {
    asm volatile("ldmatrix.sync.aligned.m8n8.x4.shared.b16 {%0,%1,%2,%3}, [%4];"
        : "=r"(r[0]), "=r"(r[1]), "=r"(r[2]), "=r"(r[3]) : "r"(addr));
}
__device__ __forceinline__ void mma16816(float* c, const uint32_t* a, uint32_t b0, uint32_t b1) {
    asm volatile("mma.sync.aligned.m16n8k16.row.col.f32.f16.f16.f32 "
        "{%0,%1,%2,%3}, {%4,%5,%6,%7}, {%8,%9}, {%0,%1,%2,%3};"
        : "+f"(c[0]), "+f"(c[1]), "+f"(c[2]), "+f"(c[3])
        : "r"(a[0]), "r"(a[1]), "r"(a[2]), "r"(a[3]), "r"(b0), "r"(b1));
}

// ================= scratch pool =================
static constexpr size_t SZ_XG  = (size_t)BB * 768 * 2;
static constexpr size_t SZ_XS  = (size_t)BB * 512 * 2;
static constexpr size_t SZ_BD  = (size_t)BB * 256 * 2;
static constexpr size_t SZ_Q0  = (size_t)2 * BB * 256 * 2;
static constexpr size_t SZ_BDF = (size_t)BB * 256 * 4;

static constexpr size_t O_XG   = 0;
static constexpr size_t O_XE   = O_XG  + SZ_XG;
static constexpr size_t O_XQS  = O_XE  + SZ_XG;
static constexpr size_t O_XRS  = O_XQS + SZ_XS;
static constexpr size_t O_XPL  = O_XRS + SZ_XS;
static constexpr size_t O_Q0H  = O_XPL + SZ_XS;
static constexpr size_t O_GHH  = O_Q0H + SZ_Q0;
static constexpr size_t O_E0H  = O_GHH + SZ_BD;
static constexpr size_t O_QSH  = O_E0H + SZ_BD;   // q0sel fp16
static constexpr size_t O_RSH  = O_QSH + SZ_BD;   // r0sel fp16
static constexpr size_t O_QSF  = O_RSH + SZ_BD;   // q0sel f32
static constexpr size_t O_RSF  = O_QSF + SZ_BDF;
static constexpr size_t SZ_W768 = (size_t)768 * 768 * 2;
static constexpr size_t SZ_W512 = (size_t)768 * 512 * 2;
static constexpr size_t SZ_W256 = (size_t)768 * 256 * 2;
static constexpr size_t O_WGIH = O_RSF + SZ_BDF;
static constexpr size_t O_WGHH = O_WGIH + SZ_W768;
static constexpr size_t O_WPIH = O_WGHH + SZ_W256;
static constexpr size_t O_WPHH = O_WPIH + SZ_W512;
static constexpr size_t O_WLIH = O_WPHH + SZ_W256;
static constexpr size_t O_WLHH = O_WLIH + SZ_W512;
static constexpr size_t O_WRIH = O_WLHH + SZ_W256;
static constexpr size_t O_WRHH = O_WRIH + SZ_W512;
static constexpr size_t O_WEIH = O_WRHH + SZ_W256;
static constexpr size_t O_WEHH = O_WEIH + SZ_W768;
static constexpr size_t O_SELROW = O_WEHH + SZ_W256;
static constexpr size_t O_QMIDX  = O_SELROW + BB * 4;
static constexpr size_t POOL_SZ  = O_QMIDX + BB * 4;

__device__ __align__(1024) unsigned char g_pool[POOL_SZ];

// ================= conv_all: f32 -> fp16 =================
struct ConvSeg { const float* src; __half* hi; int nblk; };
struct ConvTable { ConvSeg s[13]; };

__global__ void conv_all_kernel(ConvTable t) {
    int blk = blockIdx.x;
    #pragma unroll 1
    for (int i = 0; i < 13; i++) {
        int nb = t.s[i].nblk;
        if (blk < nb) {
            int idx = blk * 1024 + threadIdx.x * 4;
            float4 v = *(const float4*)(t.s[i].src + idx);
            __half2 hv0, hv1;
            hv0.x = __float2half(v.x); hv0.y = __float2half(v.y);
            hv1.x = __float2half(v.z); hv1.y = __float2half(v.w);
            *(__half2*)(t.s[i].hi + idx)     = hv0;
            *(__half2*)(t.s[i].hi + idx + 2) = hv1;
            return;
        }
        blk -= nb;
    }
}

// ================= prep =================
__global__ void prep_kernel(const float* __restrict__ U, const float* __restrict__ qmask,
                            const float* __restrict__ q0, const float* __restrict__ r0,
                            float* __restrict__ qsf, float* __restrict__ rsf,
                            __half* qsh, __half* rsh,
                            __half* xg, __half* xqs, __half* xrs, __half* xpl, __half* xe,
                            int* __restrict__ selrow, int* __restrict__ qmidx) {
    int i = blockIdx.x * 256 + threadIdx.x;
    int b = i >> 8, d = i & 255;
    int qm = (qmask[b * 2 + 1] > qmask[b * 2]) ? 1 : 0;
    if (d == 0) { qmidx[b] = qm; selrow[b] = b * 2 + qm; }
    float q = q0[(size_t)(b * 2 + qm) * DD + d];
    float r = r0[(size_t)(b * 2 + qm) * DD + d];
    float u = U[i];
    qsf[i] = q; rsf[i] = r;
    qsh[i] = __float2half(q);
    rsh[i] = __float2half(r);
    size_t o = (size_t)b * 768 + d;
    xg[o]       = __float2half(q);
    xg[o + 256] = __float2half(r);
    xg[o + 512] = __float2half(u);
    size_t o2 = (size_t)b * 512 + 256 + d;
    __half uh = __float2half(u);
    xqs[o2] = uh;
    xrs[o2] = uh;
    xpl[o2] = uh;
    xe[o]   = uh;   // xe seg0 = U
}

// ================= attention =================
__global__ void att_kernel(const float* __restrict__ gh, const float* __restrict__ attw,
                           __half* __restrict__ xrs, float* __restrict__ alpha_out) {
    extern __shared__ float sh[];
    __shared__ float s_aw[DD];
    __shared__ float s_scale[TT];
    __shared__ float s_alpha[TT];
    int b = blockIdx.x, tid = threadIdx.x;
    s_aw[tid] = attw[tid];
    for (int t = 0; t < TT; t++)
        sh[t * DD + tid] = gh[((size_t)t * BB + b) * DD + tid];
    __syncthreads();
    int w = tid >> 5, lane = tid & 31;
    for (int t = w; t < TT; t += 8) {
        float s = 0.f;
        #pragma unroll
        for (int i = 0; i < 8; i++) s += sh[t * DD + lane + i * 32] * s_aw[lane + i * 32];
        #pragma unroll
        for (int o = 16; o > 0; o >>= 1) s += __shfl_down_sync(0xffffffffu, s, o);
        if (lane == 0) s_scale[t] = s;
    }
    __syncthreads();
    if (w == 0) {
        float v0 = s_scale[lane], v1 = s_scale[lane + 32];
        float m = fmaxf(v0, v1);
        #pragma unroll
        for (int o = 16; o > 0; o >>= 1) m = fmaxf(m, __shfl_xor_sync(0xffffffffu, m, o));
        float e0 = expf(v0 - m), e1 = expf(v1 - m);
        float s = e0 + e1;
        #pragma unroll
        for (int o = 16; o > 0; o >>= 1) s += __shfl_xor_sync(0xffffffffu, s, o);
        float inv = 1.f / s;
        s_alpha[lane] = e0 * inv;
        s_alpha[lane + 32] = e1 * inv;
        alpha_out[(size_t)b * TT + lane] = e0 * inv;
        alpha_out[(size_t)b * TT + lane + 32] = e1 * inv;
    }
    __syncthreads();
    float acc = 0.f;
    for (int t = 0; t < TT; t++) acc += s_alpha[t] * sh[t * DD + tid];
    xrs[(size_t)b * 512 + tid] = __float2half(acc);
}

// ================= fused GRU — pure fp16, m32n16 warp tile =================
// Block tile: 64 rows x 64 out-cols; 8 warps = 2(m) x 4(n); warp tile 32x16.
// Stage (K=32): A(5120) + W[3 x 5120] = 20480 B. Double buffer = 40960 B.
// Per k16: 2 A-LDSM + 3 B-LDSM, 12 MMAs. One barrier per chunk.
#define ATILE 5120
#define WREG  5120
#define WTILE 5120
#define STAGE_SB 20480
#define GRU_SMEM (2 * STAGE_SB)

#define GATE2(ACCP, AF, BR) do { \
    mma16816((ACCP),     (AF), (BR)[0], (BR)[1]); \
    mma16816((ACCP) + 4, (AF), (BR)[2], (BR)[3]); \
} while (0)

__global__ __launch_bounds__(256, 2) void gru_mma_kernel(
    const __half* __restrict__ X, int K, int xshift,
    const __half* __restrict__ H, const float* __restrict__ Hf,
    const __half* __restrict__ Wih, const __half* __restrict__ Whh,
    const float* __restrict__ bih, const float* __restrict__ bhh,
    float* __restrict__ Out, const int* __restrict__ out_rows,
    const int* __restrict__ selrow, int zero_other,
    __half* __restrict__ x1, int x1_stride, int x1_off, int x1_sel,
    __half* __restrict__ x2, int x2_stride, int x2_off)
{
    extern __shared__ __align__(16) char dsm[];
    const uint32_t smb = smem_u32(dsm);

    const int tid = threadIdx.x;
    const int wid = tid >> 5, lane = tid & 31;
    const int warp_m = wid & 1, warp_n = wid >> 1;   // 2 m-warps x 4 n-warps
    const int row0 = blockIdx.x * 64, c0 = blockIdx.y * 64;

    const int nch0 = K / 32;
    const int ntot = nch0 + 8;

    float a0[16] = {}, a1[16] = {}, a2[16] = {}, a3[16] = {};

    // ---- loader setup: 4 vectors/thread/chunk (1 A + 3 W) ----
    const int lr = tid >> 2, lcv = tid & 3;
    const uint32_t sA = (uint32_t)lr * 80 + lcv * 16;
    uint32_t sW[3];
    int wgi[3], wri[3], wci[3];
    #pragma unroll
    for (int j = 0; j < 3; j++) {
        int v = tid + 256 * j;           // 0..767
        int rrow = v >> 2, c = v & 3;    // region row 0..191
        int tile = rrow >> 6;            // 0..2 (gate)
        sW[j] = WREG + (uint32_t)tile * WTILE + (uint32_t)(rrow & 63) * 80 + c * 16;
        wgi[j] = tile; wri[j] = rrow & 63; wci[j] = c;
    }
    const __half* pa = X + (size_t)((row0 + lr) >> xshift) * K + lcv * 8;
    const __half* pw[3];
    #pragma unroll
    for (int j = 0; j < 3; j++)
        pw[j] = Wih + (size_t)(wgi[j] * 256 + c0 + wri[j]) * K + wci[j] * 8;

    // ---- ldsm lane offsets (relative to stage base) ----
    const uint32_t AOFF = ((uint32_t)(warp_m * 32 + (lane & 7) + ((lane >> 3) & 1) * 8)) * 80
                        + (uint32_t)(lane >> 4) * 16;
    const uint32_t BOFF = WREG
                        + ((uint32_t)(warp_n * 16 + (lane & 7) + (lane >> 4) * 8)) * 80
                        + (uint32_t)((lane >> 3) & 1) * 16;

    #define PREF(SOFF) do { \
        cp16(smb + (SOFF) + sA,    pa); \
        cp16(smb + (SOFF) + sW[0], pw[0]); \
        cp16(smb + (SOFF) + sW[1], pw[1]); \
        cp16(smb + (SOFF) + sW[2], pw[2]); \
        pa += 32; pw[0] += 32; pw[1] += 32; pw[2] += 32; \
    } while (0)

    PREF(0);
    asm volatile("cp.async.commit_group;");

    #pragma unroll 1
    for (int i = 0; i < ntot; i++) {
        asm volatile("cp.async.wait_group 0;");
        __syncthreads();   // publish stage i; certify other stage consumed

        if (i + 1 < ntot) {
            if (i + 1 == nch0) {
                pa = H + (size_t)(row0 + lr) * 256 + lcv * 8;
                #pragma unroll
                for (int j = 0; j < 3; j++)
                    pw[j] = Whh + (size_t)(wgi[j] * 256 + c0 + wri[j]) * 256 + wci[j] * 8;
            }
            PREF(((i + 1) & 1) ? STAGE_SB : 0u);
            asm volatile("cp.async.commit_group;");
        }

        const uint32_t base = smb + ((i & 1) ? STAGE_SB : 0u);
        #pragma unroll
        for (int s = 0; s < 2; s++) {
            const uint32_t ka = (uint32_t)s * 32;
            uint32_t ah0[4], ah1[4], bf[4];
            ldsm4(ah0, base + AOFF + ka);
            ldsm4(ah1, base + AOFF + 1280 + ka);          // +16 rows
            // gate 0 -> a0
            ldsm4(bf, base + BOFF + ka);
            GATE2(a0,     ah0, bf); GATE2(a0 + 8, ah1, bf);
            // gate 1 -> a1
            ldsm4(bf, base + BOFF + WTILE + ka);
            GATE2(a1,     ah0, bf); GATE2(a1 + 8, ah1, bf);
            // gate 2 -> a2 (phase 0) or a3 (phase 1)
            ldsm4(bf, base + BOFF + 2 * WTILE + ka);
            if (i < nch0) {
                GATE2(a2,     ah0, bf); GATE2(a2 + 8, ah1, bf);
            } else {
                GATE2(a3,     ah0, bf); GATE2(a3 + 8, ah1, bf);
            }
        }
    }
    #undef PREF

    // ---- epilogue ----
    #pragma unroll
    for (int msub = 0; msub < 2; msub++) {
        const int mrowb = row0 + warp_m * 32 + msub * 16 + (lane >> 2);
        #pragma unroll
        for (int half = 0; half < 2; half++) {
            int m = mrowb + half * 8;
            int orow = out_rows ? out_rows[m] : m;
            const float* hrow = Hf + (size_t)m * 256;
            float* op = Out + (size_t)orow * 256;
            float* oo = zero_other ? (Out + (size_t)(orow ^ 1) * 256) : nullptr;
            int x1b = x1_sel ? (m >> 1) : m;
            bool x1ok = x1 && (!x1_sel || (selrow[x1b] == m));
            #pragma unroll
            for (int nt = 0; nt < 2; nt++) {
                #pragma unroll
                for (int e = 0; e < 2; e++) {
                    int col = c0 + warp_n * 16 + (lane & 3) * 2 + nt * 8 + e;
                    int d = msub * 8 + nt * 4 + half * 2 + e;
                    float ar = a0[d] + bih[col] + bhh[col];
                    float az = a1[d] + bih[256 + col] + bhh[256 + col];
                    float r = 1.f / (1.f + expf(-ar));
                    float z = 1.f / (1.f + expf(-az));
                    float n = tanhf(a2[d] + bih[512 + col] + r * (a3[d] + bhh[512 + col]));
                    float v = (1.f - z) * n + z * hrow[col];
                    op[col] = v;
                    if (oo) oo[col] = 0.f;
                    if (x1ok) x1[(size_t)x1b * x1_stride + x1_off + col] = __float2half(v);
                    if (x2)   x2[(size_t)m * x2_stride + x2_off + col]   = __float2half(v);
                }
            }
        }
    }
}

// ================= launch =================
extern "C" void kernel_launch(void* const* d_in, const int* in_sizes, int n_in,
                              void* d_out, int out_size) {
    const float* U      = (const float*)d_in[0];
    const float* qmask  = (const float*)d_in[1];
    const float* g_hist = (const float*)d_in[2];
    const float* q0     = (const float*)d_in[3];
    const float* r0     = (const float*)d_in[4];
    const float* e0     = (const float*)d_in[5];
    const float* g_wih  = (const float*)d_in[6];
    const float* g_whh  = (const float*)d_in[7];
    const float* g_bih  = (const float*)d_in[8];
    const float* g_bhh  = (const float*)d_in[9];
    const float* p_wih  = (const float*)d_in[10];
    const float* p_whh  = (const float*)d_in[11];
    const float* p_bih  = (const float*)d_in[12];
    const float* p_bhh  = (const float*)d_in[13];
    const float* pl_wih = (const float*)d_in[14];
    const float* pl_whh = (const float*)d_in[15];
    const float* pl_bih = (const float*)d_in[16];
    const float* pl_bhh = (const float*)d_in[17];
    const float* r_wih  = (const float*)d_in[18];
    const float* r_whh  = (const float*)d_in[19];
    const float* r_bih  = (const float*)d_in[20];
    const float* r_bhh  = (const float*)d_in[21];
    const float* e_wih  = (const float*)d_in[22];
    const float* e_whh  = (const float*)d_in[23];
    const float* e_bih  = (const float*)d_in[24];
    const float* e_bhh  = (const float*)d_in[25];
    const float* att_w  = (const float*)d_in[26];

    float* out = (float*)d_out;
    float* o_g = out;
    float* o_q = out + 1048576;
    float* o_r = out + 3145728;
    float* o_e = out + 5242880;
    float* o_a = out + 6291456;

    void* poolv;
    cudaGetSymbolAddress(&poolv, g_pool);
    char* pool = (char*)poolv;
    #define HF(off) ((__half*)(pool + (off)))
    #define FP(off) ((float*)(pool + (off)))
    int* selrow = (int*)(pool + O_SELROW);
    int* qmidx  = (int*)(pool + O_QMIDX);

    cudaFuncSetAttribute(att_kernel, cudaFuncAttributeMaxDynamicSharedMemorySize,
                         TT * DD * (int)sizeof(float));
    cudaFuncSetAttribute(gru_mma_kernel, cudaFuncAttributeMaxDynamicSharedMemorySize, GRU_SMEM);

    const float* ghl = g_hist + (size_t)63 * BB * DD;

    // 1) conversions: everything fp16
    ConvTable ct;
    int ti = 0, total_blk = 0;
    auto addseg = [&](const float* s, size_t oh, int n) {
        ct.s[ti].src = s; ct.s[ti].hi = HF(oh);
        ct.s[ti].nblk = n / 1024; total_blk += n / 1024; ti++;
    };
    addseg(g_wih,  O_WGIH, 768 * 768);
    addseg(g_whh,  O_WGHH, 768 * 256);
    addseg(p_wih,  O_WPIH, 768 * 512);
    addseg(p_whh,  O_WPHH, 768 * 256);
    addseg(pl_wih, O_WLIH, 768 * 512);
    addseg(pl_whh, O_WLHH, 768 * 256);
    addseg(r_wih,  O_WRIH, 768 * 512);
    addseg(r_whh,  O_WRHH, 768 * 256);
    addseg(e_wih,  O_WEIH, 768 * 768);
    addseg(e_whh,  O_WEHH, 768 * 256);
    addseg(q0,     O_Q0H,  2 * BB * 256);
    addseg(ghl,    O_GHH,  BB * 256);
    addseg(e0,     O_E0H,  BB * 256);
    conv_all_kernel<<<total_blk, 256>>>(ct);

    // 2) prep
    prep_kernel<<<BB, 256>>>(U, qmask, q0, r0,
        FP(O_QSF), FP(O_RSF), HF(O_QSH), HF(O_RSH),
        HF(O_XG), HF(O_XQS), HF(O_XRS), HF(O_XPL), HF(O_XE),
        selrow, qmidx);

    // 3) attention -> xrs first half + alpha
    att_kernel<<<BB, 256, TT * DD * sizeof(float)>>>(g_hist, att_w, HF(O_XRS), o_a);

    // 4) g GRU: K=768; epilogue writes xqs[0:256] and xe[512:768]
    gru_mma_kernel<<<dim3(BB / 64, 4), 256, GRU_SMEM>>>(
        HF(O_XG), 768, 0,
        HF(O_GHH), ghl,
        HF(O_WGIH), HF(O_WGHH),
        g_bih, g_bhh, o_g, nullptr,
        nullptr, 0,
        HF(O_XQS), 512, 0, 0,
        HF(O_XE), 768, 512);

    // 5) qs GRU: 8192 rows; epilogue writes xpl[0:256] for selected rows
    gru_mma_kernel<<<dim3(2 * BB / 64, 4), 256, GRU_SMEM>>>(
        HF(O_XQS), 512, 1,
        HF(O_Q0H), q0,
        HF(O_WPIH), HF(O_WPHH),
        p_bih, p_bhh, o_q, nullptr,
        selrow, 0,
        HF(O_XPL), 512, 0, 1,
        nullptr, 0, 0);

    // 6) rs GRU: selected rows, scatter + zero sibling row   [ncu slot 6]
    gru_mma_kernel<<<dim3(BB / 64, 4), 256, GRU_SMEM>>>(
        HF(O_XRS), 512, 0,
        HF(O_RSH), FP(O_RSF),
        HF(O_WRIH), HF(O_WRHH),
        r_bih, r_bhh, o_r, selrow,
        nullptr, 1,
        nullptr, 0, 0, 0,
        nullptr, 0, 0);

    // 7) ql GRU: selected rows, scatter into q_; epilogue writes xe[256:512]
    gru_mma_kernel<<<dim3(BB / 64, 4), 256, GRU_SMEM>>>(
        HF(O_XPL), 512, 0,
        HF(O_QSH), FP(O_QSF),
        HF(O_WLIH), HF(O_WLHH),
        pl_bih, pl_bhh, o_q, selrow,
        nullptr, 0,
        HF(O_XE), 768, 256, 0,
        nullptr, 0, 0);

    // 8) e GRU: K=768
    gru_mma_kernel<<<dim3(BB / 64, 4), 256, GRU_SMEM>>>(
        HF(O_XE), 768, 0,
        HF(O_E0H), e0,
        HF(O_WEIH), HF(O_WEHH),
        e_bih, e_bhh, o_e, nullptr,
        nullptr, 0,
        nullptr, 0, 0, 0,
        nullptr, 0, 0);
    #undef HF
    #undef FP
}